// round 3
// baseline (speedup 1.0000x reference)
#include <cuda_runtime.h>
#include <cstdint>

#define SS 7
#define NCLS 20
#define NN 98            // S*S*B
#define CONF_TH 0.1f
#define IOU_TH 0.5f
#define NTHREADS 640     // 20 warps: one warp per class for NMS/output
#define CH 30            // B*5 + NC
#define PRED_PER_BATCH (SS*SS*CH)   // 1470

// static shared memory layout (floats), total 12054 = 48216 B (< 48KB):
//   [0:9604)          iou  (98*98); first 1470 floats alias the pred staging
//                     buffer (pred is consumed in Phase B, iou written in C,
//                     separated by __syncthreads)
//   [9604:11564)      score (20*98, class-major)
//   [11564:11956)     xyxy  (98*4)
//   [11956:12054)     area  (98)
#define SM_FLOATS (9604 + 1960 + 392 + 98)

__global__ void __launch_bounds__(NTHREADS, 1)
yolo_nms_kernel(const float* __restrict__ pred, float* __restrict__ out)
{
    __shared__ float sm[SM_FLOATS];
    float* sm_iou   = sm;
    float* sm_pred  = sm;                 // aliases iou region (phase-disjoint)
    float* sm_score = sm + 9604;
    float* sm_xyxy  = sm + 9604 + 1960;
    float* sm_area  = sm_xyxy + 392;

    const int batch = blockIdx.x;
    const int tid   = threadIdx.x;
    const float* pb = pred + (size_t)batch * PRED_PER_BATCH;

    // ---- Phase A: stage pred tile (coalesced) ----
    for (int i = tid; i < PRED_PER_BATCH; i += NTHREADS) sm_pred[i] = pb[i];
    __syncthreads();

    // ---- Phase B: decode boxes + areas, compute scores ----
    if (tid < NN) {
        const int i = tid, cell = i >> 1, b = i & 1;
        const float* p = sm_pred + cell * CH + b * 5;
        const float rowf = (float)(cell / SS);
        const float colf = (float)(cell % SS);
        const float cs = 1.0f / (float)SS;
        float cx = (p[0] + rowf) * cs;
        float cy = (p[1] + colf) * cs;
        float hw = p[2] * 0.5f, hh = p[3] * 0.5f;
        float x1 = fminf(fmaxf(cx - hw, 0.0f), 1.0f);
        float y1 = fminf(fmaxf(cy - hh, 0.0f), 1.0f);
        float x2 = fminf(fmaxf(cx + hw, 0.0f), 1.0f);
        float y2 = fminf(fmaxf(cy + hh, 0.0f), 1.0f);
        sm_xyxy[i*4+0] = x1; sm_xyxy[i*4+1] = y1;
        sm_xyxy[i*4+2] = x2; sm_xyxy[i*4+3] = y2;
        sm_area[i] = (x2 - x1) * (y2 - y1);
    }
    for (int idx = tid; idx < NCLS * NN; idx += NTHREADS) {
        const int c = idx / NN;
        const int i = idx - c * NN;
        const int cell = i >> 1, b = i & 1;
        sm_score[c * NN + i] = sm_pred[cell * CH + 10 + c] * sm_pred[cell * CH + b * 5 + 4];
    }
    __syncthreads();   // pred fully consumed; iou region may now be written

    // ---- Phase C: full 98x98 IoU matrix (contiguous stripes per thread) ----
    {
        const int per = (NN * NN + NTHREADS - 1) / NTHREADS;  // 16
        int idx = tid * per;
        const int end = min(idx + per, NN * NN);
        int p = idx / NN;
        int q = idx - p * NN;
        float ax1 = 0, ay1 = 0, ax2 = 0, ay2 = 0, aar = 0;
        if (idx < end) {
            ax1 = sm_xyxy[p*4+0]; ay1 = sm_xyxy[p*4+1];
            ax2 = sm_xyxy[p*4+2]; ay2 = sm_xyxy[p*4+3];
            aar = sm_area[p];
        }
        for (; idx < end; ++idx) {
            const float bx1 = sm_xyxy[q*4+0], by1 = sm_xyxy[q*4+1];
            const float bx2 = sm_xyxy[q*4+2], by2 = sm_xyxy[q*4+3];
            const float w = fmaxf(fminf(ax2, bx2) - fmaxf(ax1, bx1), 0.0f);
            const float h = fmaxf(fminf(ay2, by2) - fmaxf(ay1, by1), 0.0f);
            const float inter = w * h;
            sm_iou[idx] = inter / (aar + sm_area[q] - inter);
            if (++q == NN) {
                q = 0; ++p;
                if (idx + 1 < end) {
                    ax1 = sm_xyxy[p*4+0]; ay1 = sm_xyxy[p*4+1];
                    ax2 = sm_xyxy[p*4+2]; ay2 = sm_xyxy[p*4+3];
                    aar = sm_area[p];
                }
            }
        }
    }
    __syncthreads();

    // ---- Phase D: per-warp greedy NMS (warp w handles class w) ----
    const int wid  = tid >> 5;
    const int lane = tid & 31;
    const int c = wid;
    const float* sc = sm_score + c * NN;
    const unsigned FULL = 0xffffffffu;

    float mys[4];
    unsigned active[4];
    unsigned keepm[4] = {0u, 0u, 0u, 0u};

    #pragma unroll
    for (int w = 0; w < 4; w++) {
        const int i = lane + 32 * w;
        float s = (i < NN) ? sc[i] : 0.0f;
        mys[w] = s;
        active[w] = __ballot_sync(FULL, (i < NN) && (s > CONF_TH));
    }

    // Iterative-max greedy NMS, equivalent to stable sort-by-score (tie ->
    // lower index) + sequential suppression. Masks replicated via ballot;
    // loop condition uniform. Hard cap of NN iterations (each iteration
    // removes >= 1 item, so the cap is unreachable in a correct run) guards
    // against any pathological hang.
    for (int iter = 0; iter < NN; ++iter) {
        if (!(active[0] | active[1] | active[2] | active[3])) break;

        // lane-local best among owned active items
        unsigned long long key = 0ull;
        #pragma unroll
        for (int w = 0; w < 4; w++) {
            if ((active[w] >> lane) & 1u) {
                const int i = lane + 32 * w;
                // positive-score float bits are order-preserving as uint;
                // low 7 bits: (127 - i) so equal scores prefer smaller index
                unsigned long long k =
                    ((unsigned long long)__float_as_uint(mys[w]) << 7) |
                    (unsigned long long)(unsigned)(127 - i);
                if (k > key) key = k;
            }
        }
        // warp max-reduce (butterfly) -> all lanes hold global best
        #pragma unroll
        for (int off = 16; off; off >>= 1) {
            unsigned long long ok = __shfl_xor_sync(FULL, key, off);
            if (ok > key) key = ok;
        }
        const int o = 127 - (int)(key & 127ull);
        keepm[o >> 5] |= 1u << (o & 31);
        active[o >> 5] &= ~(1u << (o & 31));  // kept item leaves the pool

        // suppress remaining active items with IoU(o, i) > TH
        const float* row = sm_iou + o * NN;
        #pragma unroll
        for (int w = 0; w < 4; w++) {
            const int i = lane + 32 * w;
            const bool sup = (((active[w] >> lane) & 1u) != 0u) && (row[i] > IOU_TH);
            active[w] &= ~__ballot_sync(FULL, sup);
        }
    }

    // ---- Phase E: per-warp output (class-contiguous, float2 coalesced) ----
    float* op = out + ((size_t)batch * NCLS + c) * (NN * 6);
    for (int p2 = lane; p2 < NN * 3; p2 += 32) {
        const int t = p2 / 3;
        const int part = p2 - t * 3;
        const bool kf = (keepm[t >> 5] >> (t & 31)) & 1u;
        float2 v;
        if (part == 0)      v = make_float2(sm_xyxy[t*4+0], sm_xyxy[t*4+1]);
        else if (part == 1) v = make_float2(sm_xyxy[t*4+2], sm_xyxy[t*4+3]);
        else                v = make_float2(sc[t], 1.0f);
        if (!kf) v = make_float2(0.0f, 0.0f);
        reinterpret_cast<float2*>(op)[p2] = v;
    }
}

extern "C" void kernel_launch(void* const* d_in, const int* in_sizes, int n_in,
                              void* d_out, int out_size)
{
    const float* pred = (const float*)d_in[0];
    float* out = (float*)d_out;
    const int bs = in_sizes[0] / PRED_PER_BATCH;
    yolo_nms_kernel<<<bs, NTHREADS>>>(pred, out);
}

// round 4
// speedup vs baseline: 2.2269x; 2.2269x over previous
#include <cuda_runtime.h>
#include <cstdint>

#define SS 7
#define NCLS 20
#define NN 98            // S*S*B
#define CONF_TH 0.1f
#define NTHREADS 640     // 20 warps, warp = class
#define CH 30            // B*5 + NC
#define PRED_PER_BATCH (SS*SS*CH)   // 1470

typedef unsigned long long u64;
typedef unsigned u32;

__global__ void __launch_bounds__(NTHREADS, 2)
yolo_nms_kernel(const float* __restrict__ pred, float* __restrict__ out)
{
    __shared__ float s_pred[PRED_PER_BATCH];
    __shared__ float s_x1[NN], s_y1[NN], s_x2[NN], s_y2[NN], s_area[NN];
    __shared__ float s_score[NCLS][NN];
    __shared__ u32   s_sup[NN][5];          // [][0..3] used; stride 5 = bank spread
    __shared__ u32   s_valid[NCLS][4];
    __shared__ u32   s_keep[NCLS][4];
    __shared__ unsigned char s_order[NCLS][132];  // stride 132 = bank spread

    const int batch = blockIdx.x;
    const int tid   = threadIdx.x;
    const int wid   = tid >> 5;             // = class
    const int lane  = tid & 31;
    const unsigned FULL = 0xffffffffu;
    const float* pb = pred + (size_t)batch * PRED_PER_BATCH;

    // ---- A: stage pred (coalesced) ----
    for (int i = tid; i < PRED_PER_BATCH; i += NTHREADS) s_pred[i] = pb[i];
    __syncthreads();

    // ---- B1: decode boxes -> SoA ----
    if (tid < NN) {
        const int i = tid, cell = i >> 1, b = i & 1;
        const float* p = s_pred + cell * CH + b * 5;
        const float rowf = (float)(cell / SS);
        const float colf = (float)(cell % SS);
        const float cs = 1.0f / (float)SS;
        float cx = (p[0] + rowf) * cs;
        float cy = (p[1] + colf) * cs;
        float hw = p[2] * 0.5f, hh = p[3] * 0.5f;
        float x1 = fminf(fmaxf(cx - hw, 0.0f), 1.0f);
        float y1 = fminf(fmaxf(cy - hh, 0.0f), 1.0f);
        float x2 = fminf(fmaxf(cx + hw, 0.0f), 1.0f);
        float y2 = fminf(fmaxf(cy + hh, 0.0f), 1.0f);
        s_x1[i] = x1; s_y1[i] = y1; s_x2[i] = x2; s_y2[i] = y2;
        s_area[i] = (x2 - x1) * (y2 - y1);
    }

    // ---- B2: scores + valid bitmask (warp = class) ----
    {
        const int c = wid;
        #pragma unroll
        for (int j = 0; j < 4; j++) {
            const int i = lane + 32 * j;
            float s = 0.0f;
            if (i < NN) {
                const int cell = i >> 1, b = i & 1;
                s = s_pred[cell * CH + 10 + c] * s_pred[cell * CH + b * 5 + 4];
                s_score[c][i] = s;
            }
            const u32 m = __ballot_sync(FULL, (i < NN) && (s > CONF_TH));
            if (lane == 0) s_valid[c][j] = m;
        }
    }
    __syncthreads();

    // ---- C: suppression bitmasks; warp w owns rows p = w + 20t ----
    // bit(q) of row p: IoU(p,q) > 0.5  <=>  3*inter > area_p + area_q
    for (int t = 0; t < 5; t++) {
        const int p = wid + 20 * t;
        if (p < NN) {
            const float ax1 = s_x1[p], ay1 = s_y1[p];
            const float ax2 = s_x2[p], ay2 = s_y2[p], ap = s_area[p];
            #pragma unroll
            for (int j = 0; j < 4; j++) {
                const int q = lane + 32 * j;
                bool sup = false;
                if (q < NN) {
                    float w = fminf(ax2, s_x2[q]) - fmaxf(ax1, s_x1[q]);
                    float h = fminf(ay2, s_y2[q]) - fmaxf(ay1, s_y1[q]);
                    w = fmaxf(w, 0.0f); h = fmaxf(h, 0.0f);
                    const float inter = w * h;
                    sup = (3.0f * inter > ap + s_area[q]);
                }
                const u32 m = __ballot_sync(FULL, sup);
                if (lane == 0) s_sup[p][j] = m;
            }
        }
    }

    // ---- D1: per-class bitonic sort of 128 u64 keys (descending) ----
    // key = (score_bits << 7) | (127 - i)  -> exact reference tie semantics
    {
        const int c = wid;
        u64 v[4];
        #pragma unroll
        for (int r = 0; r < 4; r++) {
            const int e = 32 * r + lane;
            float s = (e < NN) ? s_score[c][e] : 0.0f;
            v[r] = ((e < NN) && (s > CONF_TH))
                 ? ((((u64)__float_as_uint(s)) << 7) | (u64)(u32)(127 - e))
                 : 0ull;
        }
        for (int k = 2; k <= 128; k <<= 1) {
            for (int j = k >> 1; j > 0; j >>= 1) {
                if (j >= 32) {
                    const int jr = j >> 5;
                    #pragma unroll
                    for (int r = 0; r < 4; r++) {
                        if ((r & jr) == 0) {
                            const int r2 = r | jr;
                            const int e = 32 * r + lane;
                            const bool desc = ((e & k) == 0);
                            const u64 a = v[r], b = v[r2];
                            const u64 lo = (a < b) ? a : b;
                            const u64 hi = (a < b) ? b : a;
                            v[r]  = desc ? hi : lo;
                            v[r2] = desc ? lo : hi;
                        }
                    }
                } else {
                    #pragma unroll
                    for (int r = 0; r < 4; r++) {
                        const int e = 32 * r + lane;
                        const u64 o = __shfl_xor_sync(FULL, v[r], j);
                        const bool desc  = ((e & k) == 0);
                        const bool lower = ((lane & j) == 0);
                        const bool takeMax = (desc == lower);
                        const bool gt = v[r] > o;
                        v[r] = (gt == takeMax) ? v[r] : o;
                    }
                }
            }
        }
        #pragma unroll
        for (int r = 0; r < 4; r++) {
            const int e = 32 * r + lane;
            if (e < NN)
                s_order[c][e] = (unsigned char)(127 - (int)(v[r] & 127ull));
            // zero keys (invalid/pad) yield 127 -> never active in the scan
        }
    }
    __syncthreads();

    // ---- D2: serial greedy scan; ONE warp, lane = class ----
    if (wid == 0) {
        u64 actLo = 0, actHi = 0, kLo = 0, kHi = 0;
        if (lane < NCLS) {
            actLo = (u64)s_valid[lane][0] | ((u64)s_valid[lane][1] << 32);
            actHi = (u64)s_valid[lane][2] | ((u64)s_valid[lane][3] << 32);
        }
        for (int step = 0; step < NN; step++) {
            const bool any = (actLo | actHi) != 0ull;
            if (!__any_sync(FULL, any)) break;
            if (any) {
                const int o = (int)s_order[lane][step];
                const bool kept = (((o < 64) ? (actLo >> o) : (actHi >> (o - 64))) & 1ull) != 0ull;
                if (kept) {
                    if (o < 64) kLo |= 1ull << o; else kHi |= 1ull << (o - 64);
                    const u64 supLo = (u64)s_sup[o][0] | ((u64)s_sup[o][1] << 32);
                    const u64 supHi = (u64)s_sup[o][2] | ((u64)s_sup[o][3] << 32);
                    actLo &= ~supLo;
                    actHi &= ~supHi;
                }
            }
        }
        if (lane < NCLS) {
            s_keep[lane][0] = (u32)kLo; s_keep[lane][1] = (u32)(kLo >> 32);
            s_keep[lane][2] = (u32)kHi; s_keep[lane][3] = (u32)(kHi >> 32);
        }
    }
    __syncthreads();

    // ---- E: output, warp = class, float2 coalesced ----
    {
        const int c = wid;
        const u64 kpLo = (u64)s_keep[c][0] | ((u64)s_keep[c][1] << 32);
        const u64 kpHi = (u64)s_keep[c][2] | ((u64)s_keep[c][3] << 32);
        float* op = out + ((size_t)batch * NCLS + c) * (NN * 6);
        for (int p2 = lane; p2 < NN * 3; p2 += 32) {
            const int t = p2 / 3;
            const int part = p2 - 3 * t;
            const bool kf = (((t < 64) ? (kpLo >> t) : (kpHi >> (t - 64))) & 1ull) != 0ull;
            float2 v;
            if (part == 0)      v = make_float2(s_x1[t], s_y1[t]);
            else if (part == 1) v = make_float2(s_x2[t], s_y2[t]);
            else                v = make_float2(s_score[c][t], 1.0f);
            if (!kf) v = make_float2(0.0f, 0.0f);
            reinterpret_cast<float2*>(op)[p2] = v;
        }
    }
}

extern "C" void kernel_launch(void* const* d_in, const int* in_sizes, int n_in,
                              void* d_out, int out_size)
{
    const float* pred = (const float*)d_in[0];
    float* out = (float*)d_out;
    const int bs = in_sizes[0] / PRED_PER_BATCH;
    yolo_nms_kernel<<<bs, NTHREADS>>>(pred, out);
}

// round 5
// speedup vs baseline: 2.2974x; 1.0317x over previous
#include <cuda_runtime.h>
#include <cstdint>

#define SS 7
#define NCLS 20
#define NN 98            // S*S*B
#define CONF_TH 0.1f
#define NTHREADS 640     // 20 warps, warp = class
#define CH 30            // B*5 + NC
#define PRED_PER_BATCH (SS*SS*CH)   // 1470
#define SCORE_BASE 0x3DCCCCCDu      // float bits of 0.1f

typedef unsigned u32;
typedef unsigned long long u64;

__global__ void __launch_bounds__(NTHREADS, 3)
yolo_nms_kernel(const float* __restrict__ pred, float* __restrict__ out)
{
    __shared__ float s_pred[PRED_PER_BATCH];
    __shared__ float s_x1[NN], s_y1[NN], s_x2[NN], s_y2[NN], s_area[NN];
    __shared__ float s_score[NCLS][NN];
    __shared__ uint4 s_sup[NN];          // row p: suppression bitmask over q
    __shared__ u32   s_valid[NCLS][4];

    const int batch = blockIdx.x;
    const int tid   = threadIdx.x;
    const int wid   = tid >> 5;          // = class
    const int lane  = tid & 31;
    const unsigned FULL = 0xffffffffu;
    const float* pb = pred + (size_t)batch * PRED_PER_BATCH;

    // ---- A: stage pred (coalesced) ----
    for (int i = tid; i < PRED_PER_BATCH; i += NTHREADS) s_pred[i] = pb[i];
    __syncthreads();

    // ---- B1: decode boxes -> SoA ----
    if (tid < NN) {
        const int i = tid, cell = i >> 1, b = i & 1;
        const float* p = s_pred + cell * CH + b * 5;
        const float rowf = (float)(cell / SS);
        const float colf = (float)(cell % SS);
        const float cs = 1.0f / (float)SS;
        float cx = (p[0] + rowf) * cs;
        float cy = (p[1] + colf) * cs;
        float hw = p[2] * 0.5f, hh = p[3] * 0.5f;
        float x1 = fminf(fmaxf(cx - hw, 0.0f), 1.0f);
        float y1 = fminf(fmaxf(cy - hh, 0.0f), 1.0f);
        float x2 = fminf(fmaxf(cx + hw, 0.0f), 1.0f);
        float y2 = fminf(fmaxf(cy + hh, 0.0f), 1.0f);
        s_x1[i] = x1; s_y1[i] = y1; s_x2[i] = x2; s_y2[i] = y2;
        s_area[i] = (x2 - x1) * (y2 - y1);
    }

    // ---- B2: scores + valid bitmasks (warp = class) ----
    {
        const int c = wid;
        #pragma unroll
        for (int j = 0; j < 4; j++) {
            const int i = lane + 32 * j;
            float s = 0.0f;
            if (i < NN) {
                const int cell = i >> 1, b = i & 1;
                s = s_pred[cell * CH + 10 + c] * s_pred[cell * CH + b * 5 + 4];
                s_score[c][i] = s;
            }
            const u32 m = __ballot_sync(FULL, (i < NN) && (s > CONF_TH));
            if (lane == 0) s_valid[c][j] = m;
        }
    }
    __syncthreads();

    // ---- C: suppression bitmasks; warp w owns rows p = w + 20t ----
    // bit(q) of row p: IoU(p,q) > 0.5  <=>  3*inter > area_p + area_q
    // (division-free, validated in R4: identical rel_err to the division form)
    {
        // lane-held q boxes (loaded once)
        float qx1[4], qy1[4], qx2[4], qy2[4], qa[4];
        #pragma unroll
        for (int j = 0; j < 4; j++) {
            const int q = lane + 32 * j;
            const int qc = (q < NN) ? q : 0;
            qx1[j] = s_x1[qc]; qy1[j] = s_y1[qc];
            qx2[j] = s_x2[qc]; qy2[j] = s_y2[qc];
            qa[j]  = s_area[qc];
        }
        #pragma unroll
        for (int t = 0; t < 5; t++) {
            const int p = wid + 20 * t;
            if (p < NN) {
                const float ax1 = s_x1[p], ay1 = s_y1[p];
                const float ax2 = s_x2[p], ay2 = s_y2[p], ap = s_area[p];
                u32 m[4];
                #pragma unroll
                for (int j = 0; j < 4; j++) {
                    const int q = lane + 32 * j;
                    float w = fminf(ax2, qx2[j]) - fmaxf(ax1, qx1[j]);
                    float h = fminf(ay2, qy2[j]) - fmaxf(ay1, qy1[j]);
                    w = fmaxf(w, 0.0f); h = fmaxf(h, 0.0f);
                    const float inter = w * h;
                    const bool sup = (q < NN) && (3.0f * inter > ap + qa[j]);
                    m[j] = __ballot_sync(FULL, sup);
                }
                if (lane == 0) s_sup[p] = make_uint4(m[0], m[1], m[2], m[3]);
            }
        }
    }
    __syncthreads();

    // ---- D: per-warp iterative-max greedy NMS (warp = class) ----
    // Replicated masks: every lane holds identical act/keep; updates come
    // from broadcast shfl-max results and broadcast LDS.128 of sup rows —
    // no ballots, no smem writes in the loop. Exact reference semantics:
    // stable descending-score order (tie -> lower index via 127-i suffix).
    u32 keep0 = 0, keep1 = 0, keep2 = 0, keep3 = 0;
    {
        const int c = wid;
        u32 act[4];
        #pragma unroll
        for (int w = 0; w < 4; w++) act[w] = s_valid[c][w];

        // u32 keys: valid scores in (0.1, 1] -> (bits - BASE) < 2^25, so
        // ((bits - BASE) << 7) | (127 - i) fits 32 bits, order-preserving.
        u32 k[4];
        #pragma unroll
        for (int w = 0; w < 4; w++) {
            const int i = lane + 32 * w;
            const float s = (i < NN) ? s_score[c][i] : 0.0f;
            k[w] = ((__float_as_uint(s) - SCORE_BASE) << 7) | (u32)(127 - i);
            // garbage when inactive; masked by act below
        }

        while (true) {
            u32 m = 0;
            #pragma unroll
            for (int w = 0; w < 4; w++)
                if ((act[w] >> lane) & 1u) m = (k[w] > m) ? k[w] : m;
            #pragma unroll
            for (int off = 16; off; off >>= 1) {
                const u32 o = __shfl_xor_sync(FULL, m, off);
                m = (o > m) ? o : m;
            }
            if (m == 0u) break;               // no active items (keys are >0)
            const int o = 127 - (int)(m & 127u);
            const u32 ob = 1u << (o & 31);
            const int ow = o >> 5;
            // set keep bit, clear picked bit (guarantees termination)
            keep0 |= (ow == 0) ? ob : 0u;  keep1 |= (ow == 1) ? ob : 0u;
            keep2 |= (ow == 2) ? ob : 0u;  keep3 |= (ow == 3) ? ob : 0u;
            const uint4 sup = s_sup[o];       // broadcast LDS.128
            act[0] &= ~(sup.x | ((ow == 0) ? ob : 0u));
            act[1] &= ~(sup.y | ((ow == 1) ? ob : 0u));
            act[2] &= ~(sup.z | ((ow == 2) ? ob : 0u));
            act[3] &= ~(sup.w | ((ow == 3) ? ob : 0u));
        }
    }

    // ---- E: output, warp = class, float2 coalesced (no barrier needed) ----
    {
        const int c = wid;
        const u64 kpLo = (u64)keep0 | ((u64)keep1 << 32);
        const u64 kpHi = (u64)keep2 | ((u64)keep3 << 32);
        float* op = out + ((size_t)batch * NCLS + c) * (NN * 6);
        for (int p2 = lane; p2 < NN * 3; p2 += 32) {
            const int t = p2 / 3;
            const int part = p2 - 3 * t;
            const bool kf = (((t < 64) ? (kpLo >> t) : (kpHi >> (t - 64))) & 1ull) != 0ull;
            float2 v;
            if (part == 0)      v = make_float2(s_x1[t], s_y1[t]);
            else if (part == 1) v = make_float2(s_x2[t], s_y2[t]);
            else                v = make_float2(s_score[c][t], 1.0f);
            if (!kf) v = make_float2(0.0f, 0.0f);
            reinterpret_cast<float2*>(op)[p2] = v;
        }
    }
}

extern "C" void kernel_launch(void* const* d_in, const int* in_sizes, int n_in,
                              void* d_out, int out_size)
{
    const float* pred = (const float*)d_in[0];
    float* out = (float*)d_out;
    const int bs = in_sizes[0] / PRED_PER_BATCH;
    yolo_nms_kernel<<<bs, NTHREADS>>>(pred, out);
}

// round 6
// speedup vs baseline: 4.4883x; 1.9536x over previous
#include <cuda_runtime.h>
#include <cstdint>

#define SS 7
#define NCLS 20
#define NN 98            // S*S*B
#define CONF_TH 0.1f
#define NTHREADS 640     // 20 warps, warp = class
#define CH 30            // B*5 + NC
#define PRED_PER_BATCH (SS*SS*CH)   // 1470
#define SCORE_BASE 0x3DCCCCCDu      // float bits of 0.1f

typedef unsigned u32;
typedef unsigned long long u64;

__global__ void __launch_bounds__(NTHREADS, 3)
yolo_nms_kernel(const float* __restrict__ pred, float* __restrict__ out)
{
    __shared__ float s_pred[PRED_PER_BATCH];
    __shared__ float s_x1[NN], s_y1[NN], s_x2[NN], s_y2[NN], s_area[NN];
    __shared__ float s_score[NCLS][NN];
    __shared__ uint4 s_sup[NN];          // row p: suppression bitmask over q
    __shared__ u32   s_valid[NCLS][4];

    const int batch = blockIdx.x;
    const int tid   = threadIdx.x;
    const int wid   = tid >> 5;          // = class
    const int lane  = tid & 31;
    const unsigned FULL = 0xffffffffu;
    const u32 lane_bit = 1u << lane;
    const float* pb = pred + (size_t)batch * PRED_PER_BATCH;

    // ---- A: stage pred (coalesced) ----
    for (int i = tid; i < PRED_PER_BATCH; i += NTHREADS) s_pred[i] = pb[i];
    __syncthreads();

    // ---- B1: decode boxes -> SoA ----
    if (tid < NN) {
        const int i = tid, cell = i >> 1, b = i & 1;
        const float* p = s_pred + cell * CH + b * 5;
        const float rowf = (float)(cell / SS);
        const float colf = (float)(cell % SS);
        const float cs = 1.0f / (float)SS;
        float cx = (p[0] + rowf) * cs;
        float cy = (p[1] + colf) * cs;
        float hw = p[2] * 0.5f, hh = p[3] * 0.5f;
        float x1 = fminf(fmaxf(cx - hw, 0.0f), 1.0f);
        float y1 = fminf(fmaxf(cy - hh, 0.0f), 1.0f);
        float x2 = fminf(fmaxf(cx + hw, 0.0f), 1.0f);
        float y2 = fminf(fmaxf(cy + hh, 0.0f), 1.0f);
        s_x1[i] = x1; s_y1[i] = y1; s_x2[i] = x2; s_y2[i] = y2;
        s_area[i] = (x2 - x1) * (y2 - y1);
    }

    // ---- B2: scores + valid bitmasks (warp = class) ----
    {
        const int c = wid;
        #pragma unroll
        for (int j = 0; j < 4; j++) {
            const int i = lane + 32 * j;
            float s = 0.0f;
            if (i < NN) {
                const int cell = i >> 1, b = i & 1;
                s = s_pred[cell * CH + 10 + c] * s_pred[cell * CH + b * 5 + 4];
                s_score[c][i] = s;
            }
            const u32 m = __ballot_sync(FULL, (i < NN) && (s > CONF_TH));
            if (lane == 0) s_valid[c][j] = m;
        }
    }
    __syncthreads();

    // ---- C: suppression bitmasks; warp w owns rows p = w + 20t ----
    // bit(q) of row p: IoU(p,q) > 0.5  <=>  3*inter > area_p + area_q
    // (division-free; symmetric by construction: min/max args identical)
    {
        float qx1[4], qy1[4], qx2[4], qy2[4], qa[4];
        #pragma unroll
        for (int j = 0; j < 4; j++) {
            const int q = lane + 32 * j;
            const int qc = (q < NN) ? q : 0;
            qx1[j] = s_x1[qc]; qy1[j] = s_y1[qc];
            qx2[j] = s_x2[qc]; qy2[j] = s_y2[qc];
            qa[j]  = s_area[qc];
        }
        #pragma unroll
        for (int t = 0; t < 5; t++) {
            const int p = wid + 20 * t;
            if (p < NN) {
                const float ax1 = s_x1[p], ay1 = s_y1[p];
                const float ax2 = s_x2[p], ay2 = s_y2[p], ap = s_area[p];
                u32 m[4];
                #pragma unroll
                for (int j = 0; j < 4; j++) {
                    const int q = lane + 32 * j;
                    float w = fminf(ax2, qx2[j]) - fmaxf(ax1, qx1[j]);
                    float h = fminf(ay2, qy2[j]) - fmaxf(ay1, qy1[j]);
                    w = fmaxf(w, 0.0f); h = fmaxf(h, 0.0f);
                    const float inter = w * h;
                    const bool sup = (q < NN) && (3.0f * inter > ap + qa[j]);
                    m[j] = __ballot_sync(FULL, sup);
                }
                if (lane == 0) s_sup[p] = make_uint4(m[0], m[1], m[2], m[3]);
            }
        }
    }
    __syncthreads();

    // ---- D: per-warp greedy NMS (warp = class) ----
    u32 keep0 = 0, keep1 = 0, keep2 = 0, keep3 = 0;
    {
        const int c = wid;
        u32 act[4];
        #pragma unroll
        for (int w = 0; w < 4; w++) act[w] = s_valid[c][w];

        // D0: isolation pass. sup is symmetric, so an active box whose
        // sup row intersects act only at itself can neither suppress nor
        // be suppressed: keep it unconditionally and drop it from act.
        // This leaves only the (small) mutually-conflicting subset for
        // the serial pick loop.
        {
            u32 iso[4];
            #pragma unroll
            for (int w = 0; w < 4; w++) {
                const int i = lane + 32 * w;
                bool is_iso = false;
                if (act[w] & lane_bit) {          // implies i < NN
                    const uint4 sup = s_sup[i];
                    u32 c0 = sup.x & act[0];
                    u32 c1 = sup.y & act[1];
                    u32 c2 = sup.z & act[2];
                    u32 c3 = sup.w & act[3];
                    // clear self bit (word w, position lane)
                    if (w == 0) c0 &= ~lane_bit;
                    else if (w == 1) c1 &= ~lane_bit;
                    else if (w == 2) c2 &= ~lane_bit;
                    else c3 &= ~lane_bit;
                    is_iso = ((c0 | c1 | c2 | c3) == 0u);
                }
                iso[w] = __ballot_sync(FULL, is_iso);
            }
            keep0 |= iso[0]; keep1 |= iso[1]; keep2 |= iso[2]; keep3 |= iso[3];
            #pragma unroll
            for (int w = 0; w < 4; w++) act[w] &= ~iso[w];
        }

        // D1: iterative-max pick loop on the conflicted remainder.
        // u32 keys: valid scores in (0.1, 1] -> (bits - BASE) < 2^25, so
        // ((bits - BASE) << 7) | (127 - i) is order-preserving with the
        // reference's exact tie semantics (tie -> lower index).
        u32 k[4];
        #pragma unroll
        for (int w = 0; w < 4; w++) {
            const int i = lane + 32 * w;
            const float s = (i < NN) ? s_score[c][i] : 0.0f;
            k[w] = ((__float_as_uint(s) - SCORE_BASE) << 7) | (u32)(127 - i);
        }

        while (act[0] | act[1] | act[2] | act[3]) {
            u32 m = 0;
            #pragma unroll
            for (int w = 0; w < 4; w++)
                if (act[w] & lane_bit) m = (k[w] > m) ? k[w] : m;
            #pragma unroll
            for (int off = 16; off; off >>= 1) {
                const u32 o = __shfl_xor_sync(FULL, m, off);
                m = (o > m) ? o : m;
            }
            const int o = 127 - (int)(m & 127u);
            const u32 ob = 1u << (o & 31);
            const int ow = o >> 5;
            keep0 |= (ow == 0) ? ob : 0u;  keep1 |= (ow == 1) ? ob : 0u;
            keep2 |= (ow == 2) ? ob : 0u;  keep3 |= (ow == 3) ? ob : 0u;
            const uint4 sup = s_sup[o];       // broadcast LDS.128
            act[0] &= ~(sup.x | ((ow == 0) ? ob : 0u));
            act[1] &= ~(sup.y | ((ow == 1) ? ob : 0u));
            act[2] &= ~(sup.z | ((ow == 2) ? ob : 0u));
            act[3] &= ~(sup.w | ((ow == 3) ? ob : 0u));
        }
    }

    // ---- E: output, warp = class, float2 coalesced (no barrier needed) ----
    {
        const int c = wid;
        const u64 kpLo = (u64)keep0 | ((u64)keep1 << 32);
        const u64 kpHi = (u64)keep2 | ((u64)keep3 << 32);
        float* op = out + ((size_t)batch * NCLS + c) * (NN * 6);
        for (int p2 = lane; p2 < NN * 3; p2 += 32) {
            const int t = p2 / 3;
            const int part = p2 - 3 * t;
            const bool kf = (((t < 64) ? (kpLo >> t) : (kpHi >> (t - 64))) & 1ull) != 0ull;
            float2 v;
            if (part == 0)      v = make_float2(s_x1[t], s_y1[t]);
            else if (part == 1) v = make_float2(s_x2[t], s_y2[t]);
            else                v = make_float2(s_score[c][t], 1.0f);
            if (!kf) v = make_float2(0.0f, 0.0f);
            reinterpret_cast<float2*>(op)[p2] = v;
        }
    }
}

extern "C" void kernel_launch(void* const* d_in, const int* in_sizes, int n_in,
                              void* d_out, int out_size)
{
    const float* pred = (const float*)d_in[0];
    float* out = (float*)d_out;
    const int bs = in_sizes[0] / PRED_PER_BATCH;
    yolo_nms_kernel<<<bs, NTHREADS>>>(pred, out);
}

// round 7
// speedup vs baseline: 5.6048x; 1.2488x over previous
#include <cuda_runtime.h>
#include <cstdint>

#define SS 7
#define NCLS 20
#define NN 98            // S*S*B
#define CONF_TH 0.1f
#define NTHREADS 640     // 20 warps, warp = class
#define CH 30            // B*5 + NC
#define PRED_PER_BATCH (SS*SS*CH)   // 1470
#define SCORE_BASE 0x3DCCCCCDu      // float bits of 0.1f

typedef unsigned u32;
typedef unsigned long long u64;

__global__ void __launch_bounds__(NTHREADS, 3)
yolo_nms_kernel(const float* __restrict__ pred, float* __restrict__ out)
{
    __shared__ float  s_pred[PRED_PER_BATCH];
    __shared__ float4 s_box[NN];         // (x1, y1, x2, y2)
    __shared__ float  s_area[NN];
    __shared__ u32    s_key[NCLS][NN];   // 0 if invalid; else ((bits-BASE)<<7)|(127-i)
    __shared__ uint4  s_sup[NN];         // row p: IoU(p,q) > 0.5 bitmask
    __shared__ u32    s_valid[NCLS][4];

    const int batch = blockIdx.x;
    const int tid   = threadIdx.x;
    const int wid   = tid >> 5;          // = class
    const int lane  = tid & 31;
    const unsigned FULL = 0xffffffffu;
    const u32 lane_bit = 1u << lane;
    const float* pb = pred + (size_t)batch * PRED_PER_BATCH;

    // ---- A: stage pred (coalesced) ----
    for (int i = tid; i < PRED_PER_BATCH; i += NTHREADS) s_pred[i] = pb[i];
    __syncthreads();

    // ---- B1: decode boxes -> AoS float4 + area ----
    if (tid < NN) {
        const int i = tid, cell = i >> 1, b = i & 1;
        const float* p = s_pred + cell * CH + b * 5;
        const float rowf = (float)(cell / SS);
        const float colf = (float)(cell % SS);
        const float cs = 1.0f / (float)SS;
        float cx = (p[0] + rowf) * cs;
        float cy = (p[1] + colf) * cs;
        float hw = p[2] * 0.5f, hh = p[3] * 0.5f;
        float x1 = fminf(fmaxf(cx - hw, 0.0f), 1.0f);
        float y1 = fminf(fmaxf(cy - hh, 0.0f), 1.0f);
        float x2 = fminf(fmaxf(cx + hw, 0.0f), 1.0f);
        float y2 = fminf(fmaxf(cy + hh, 0.0f), 1.0f);
        s_box[i] = make_float4(x1, y1, x2, y2);
        s_area[i] = (x2 - x1) * (y2 - y1);
    }

    // ---- B2: keys + valid bitmasks (warp = class) ----
    // key preserves exact reference order incl. tie -> lower index:
    // valid scores in (0.1, 1] -> (bits - BASE) < 2^25 -> <<7 fits u32.
    {
        const int c = wid;
        #pragma unroll
        for (int j = 0; j < 4; j++) {
            const int i = lane + 32 * j;
            u32 key = 0;
            if (i < NN) {
                const int cell = i >> 1, b = i & 1;
                const float s = s_pred[cell * CH + 10 + c] * s_pred[cell * CH + b * 5 + 4];
                if (s > CONF_TH)
                    key = ((__float_as_uint(s) - SCORE_BASE) << 7) | (u32)(127 - i);
                s_key[c][i] = key;
            }
            const u32 m = __ballot_sync(FULL, key != 0u);
            if (lane == 0) s_valid[c][j] = m;
        }
    }
    __syncthreads();

    // ---- C: suppression bitmasks; warp w owns rows p = w + 20t ----
    // bit(q) of row p: IoU(p,q) > 0.5  <=>  3*inter > area_p + area_q
    // (division-free; symmetric: float eval identical both directions)
    {
        float4 qb[4]; float qa[4];
        #pragma unroll
        for (int j = 0; j < 4; j++) {
            const int q = lane + 32 * j;
            const int qc = (q < NN) ? q : 0;
            qb[j] = s_box[qc]; qa[j] = s_area[qc];
        }
        #pragma unroll
        for (int t = 0; t < 5; t++) {
            const int p = wid + 20 * t;
            if (p < NN) {
                const float4 a = s_box[p];
                const float ap = s_area[p];
                u32 m[4];
                #pragma unroll
                for (int j = 0; j < 4; j++) {
                    const int q = lane + 32 * j;
                    float w = fminf(a.z, qb[j].z) - fmaxf(a.x, qb[j].x);
                    float h = fminf(a.w, qb[j].w) - fmaxf(a.y, qb[j].y);
                    w = fmaxf(w, 0.0f); h = fmaxf(h, 0.0f);
                    const float inter = w * h;
                    const bool sup = (q < NN) && (3.0f * inter > ap + qa[j]);
                    m[j] = __ballot_sync(FULL, sup);
                }
                if (lane == 0) s_sup[p] = make_uint4(m[0], m[1], m[2], m[3]);
            }
        }
    }
    __syncthreads();

    // ---- D: iterated local-max NMS (exactly == sequential greedy) ----
    // Each pass keeps every active box whose key beats all active
    // neighbors (greedy picks it before any neighbor), then removes the
    // kept boxes and everything they suppress. Unique keys -> no ties.
    // Global max is always a local max -> >=1 removal/pass -> <=NN passes.
    u32 keep0 = 0, keep1 = 0, keep2 = 0, keep3 = 0;
    {
        const int c = wid;
        u32 act[4], k[4];
        #pragma unroll
        for (int w = 0; w < 4; w++) {
            act[w] = s_valid[c][w];
            const int i = lane + 32 * w;
            k[w] = (i < NN) ? s_key[c][i] : 0u;
        }
        for (int pass = 0; pass < NN; ++pass) {
            if (!(act[0] | act[1] | act[2] | act[3])) break;
            u32 lm[4];
            #pragma unroll
            for (int w = 0; w < 4; w++) {
                bool is_lm = false;
                if (act[w] & lane_bit) {
                    const int i = lane + 32 * w;
                    const uint4 row = s_sup[i];
                    u32 n0 = row.x & act[0];
                    u32 n1 = row.y & act[1];
                    u32 n2 = row.z & act[2];
                    u32 n3 = row.w & act[3];
                    if (w == 0) n0 &= ~lane_bit;
                    else if (w == 1) n1 &= ~lane_bit;
                    else if (w == 2) n2 &= ~lane_bit;
                    else n3 &= ~lane_bit;
                    u32 mk = 0;
                    while (n0) { const int q = __ffs(n0) - 1;  n0 &= n0 - 1; mk = max(mk, s_key[c][q]); }
                    while (n1) { const int q = __ffs(n1) + 31; n1 &= n1 - 1; mk = max(mk, s_key[c][q]); }
                    while (n2) { const int q = __ffs(n2) + 63; n2 &= n2 - 1; mk = max(mk, s_key[c][q]); }
                    while (n3) { const int q = __ffs(n3) + 95; n3 &= n3 - 1; mk = max(mk, s_key[c][q]); }
                    is_lm = (k[w] > mk);
                }
                lm[w] = __ballot_sync(FULL, is_lm);
            }
            keep0 |= lm[0]; keep1 |= lm[1]; keep2 |= lm[2]; keep3 |= lm[3];
            #pragma unroll
            for (int w = 0; w < 4; w++) {
                bool rem = false;
                if (act[w] & lane_bit) {
                    const uint4 row = s_sup[lane + 32 * w];
                    rem = ((row.x & lm[0]) | (row.y & lm[1]) |
                           (row.z & lm[2]) | (row.w & lm[3])) != 0u;
                    // kept boxes remove themselves via their own row's self bit
                }
                act[w] &= ~__ballot_sync(FULL, rem);
            }
        }
    }

    // ---- E: output, warp = class, float4 stores ----
    // Row per box: [x1,y1,x2,y2,score,keep]*keep. 2 boxes = 3 float4:
    //   part0: box t   {x1,y1,x2,y2}
    //   part1: box t   {score,keep} + box t+1 {x1,y1}
    //   part2: box t+1 {x2,y2,score,keep}
    {
        const int c = wid;
        const u64 kpLo = (u64)keep0 | ((u64)keep1 << 32);
        const u64 kpHi = (u64)keep2 | ((u64)keep3 << 32);
        float4* op = reinterpret_cast<float4*>(out + ((size_t)batch * NCLS + c) * (NN * 6));
        #pragma unroll
        for (int it = 0; it < 5; ++it) {
            const int v4 = lane + 32 * it;
            if (v4 < 147) {
                const int g = v4 / 3;
                const int part = v4 - 3 * g;
                const int t = 2 * g;
                const bool kf0 = (((t < 64) ? (kpLo >> t) : (kpHi >> (t - 64))) & 1ull) != 0ull;
                const bool kf1 = (((t + 1 < 64) ? (kpLo >> (t + 1)) : (kpHi >> (t - 63))) & 1ull) != 0ull;
                float4 v;
                if (part == 0) {
                    v = kf0 ? s_box[t] : make_float4(0.f, 0.f, 0.f, 0.f);
                } else if (part == 1) {
                    float sc0 = 0.f;
                    if (kf0) sc0 = __uint_as_float((s_key[c][t] >> 7) + SCORE_BASE);
                    const float4 b1 = s_box[t + 1];
                    v = make_float4(sc0, kf0 ? 1.f : 0.f,
                                    kf1 ? b1.x : 0.f, kf1 ? b1.y : 0.f);
                } else {
                    const float4 b1 = s_box[t + 1];
                    float sc1 = 0.f;
                    if (kf1) sc1 = __uint_as_float((s_key[c][t + 1] >> 7) + SCORE_BASE);
                    v = make_float4(kf1 ? b1.z : 0.f, kf1 ? b1.w : 0.f,
                                    sc1, kf1 ? 1.f : 0.f);
                }
                op[v4] = v;
            }
        }
    }
}

extern "C" void kernel_launch(void* const* d_in, const int* in_sizes, int n_in,
                              void* d_out, int out_size)
{
    const float* pred = (const float*)d_in[0];
    float* out = (float*)d_out;
    const int bs = in_sizes[0] / PRED_PER_BATCH;
    yolo_nms_kernel<<<bs, NTHREADS>>>(pred, out);
}

// round 8
// speedup vs baseline: 6.2781x; 1.1201x over previous
#include <cuda_runtime.h>
#include <cstdint>

#define SS 7
#define NCLS 20
#define NN 98            // S*S*B
#define NP 128           // padded box count
#define CONF_TH 0.1f
#define NTHREADS 640     // 20 warps, warp = class
#define CH 30            // B*5 + NC
#define PRED_PER_BATCH (SS*SS*CH)   // 1470
#define SCORE_BASE 0x3DCCCCCDu      // float bits of 0.1f

typedef unsigned u32;
typedef unsigned long long u64;

__global__ void __launch_bounds__(NTHREADS, 3)
yolo_nms_kernel(const float* __restrict__ pred, float* __restrict__ out)
{
    __shared__ float  s_pred[PRED_PER_BATCH + 2];
    __shared__ float4 s_box[NP];         // (x1,y1,x2,y2); NaN for pads
    __shared__ float  s_area[NP];        // NaN for pads
    __shared__ u32    s_key[NCLS][NP];   // 0 invalid/pad; ((bits-BASE)<<7)|(127-i)
    __shared__ uint4  s_sup[NN];         // row p: IoU(p,q) > 0.5 bitmask

    const int batch = blockIdx.x;
    const int tid   = threadIdx.x;
    const int wid   = tid >> 5;          // = class
    const int lane  = tid & 31;
    const unsigned FULL = 0xffffffffu;
    const u32 lane_bit = 1u << lane;

    // ---- A: stage pred (float2, coalesced; 1470 floats = 735 f2) ----
    {
        const float2* pb2 = reinterpret_cast<const float2*>(pred + (size_t)batch * PRED_PER_BATCH);
        float2* sp2 = reinterpret_cast<float2*>(s_pred);
        if (tid < 735 - NTHREADS + NTHREADS) { // always true; keep simple strided loop
            sp2[tid] = (tid < 735) ? pb2[tid] : make_float2(0.f, 0.f);
            const int i2 = tid + NTHREADS;
            if (i2 < 735) sp2[i2] = pb2[i2];
        }
    }
    __syncthreads();

    // ---- B1: decode boxes -> AoS float4 + area; NaN pads for i >= NN ----
    if (tid < NP) {
        const int i = tid;
        if (i < NN) {
            const int cell = i >> 1, b = i & 1;
            const float* p = s_pred + cell * CH + b * 5;
            const float rowf = (float)(cell / SS);
            const float colf = (float)(cell % SS);
            const float cs = 1.0f / (float)SS;
            float cx = (p[0] + rowf) * cs;
            float cy = (p[1] + colf) * cs;
            float hw = p[2] * 0.5f, hh = p[3] * 0.5f;
            float x1 = fminf(fmaxf(cx - hw, 0.0f), 1.0f);
            float y1 = fminf(fmaxf(cy - hh, 0.0f), 1.0f);
            float x2 = fminf(fmaxf(cx + hw, 0.0f), 1.0f);
            float y2 = fminf(fmaxf(cy + hh, 0.0f), 1.0f);
            s_box[i] = make_float4(x1, y1, x2, y2);
            s_area[i] = (x2 - x1) * (y2 - y1);
        } else {
            const float qn = __uint_as_float(0x7FC00000u);   // NaN
            s_box[i] = make_float4(qn, qn, qn, qn);
            s_area[i] = qn;                                  // makes sup bit false
        }
    }

    // ---- B2: keys (warp = class); zero for invalid and pads ----
    // key preserves exact reference order incl. tie -> lower index:
    // valid scores in (0.1, 1] -> (bits - BASE) < 2^25 -> <<7 fits u32.
    {
        const int c = wid;
        #pragma unroll
        for (int j = 0; j < 4; j++) {
            const int i = lane + 32 * j;
            u32 key = 0;
            if (i < NN) {
                const int cell = i >> 1, b = i & 1;
                const float s = s_pred[cell * CH + 10 + c] * s_pred[cell * CH + b * 5 + 4];
                if (s > CONF_TH)
                    key = ((__float_as_uint(s) - SCORE_BASE) << 7) | (u32)(127 - i);
            }
            s_key[c][i] = key;
        }
    }
    __syncthreads();

    // ---- C: suppression bitmasks; warp w owns rows p = w + 20t ----
    // bit(q): IoU(p,q) > 0.5  <=>  3*inter > area_p + area_q (division-free,
    // symmetric). NaN pad areas make pad bits false with no predicate.
    {
        float4 qb[4]; float qa[4];
        #pragma unroll
        for (int j = 0; j < 4; j++) {
            const int q = lane + 32 * j;
            qb[j] = s_box[q]; qa[j] = s_area[q];
        }
        #pragma unroll
        for (int t = 0; t < 5; t++) {
            const int p = wid + 20 * t;
            if (p < NN) {
                const float4 a = s_box[p];
                const float ap = s_area[p];
                u32 m[4];
                #pragma unroll
                for (int j = 0; j < 4; j++) {
                    float w = fminf(a.z, qb[j].z) - fmaxf(a.x, qb[j].x);
                    float h = fminf(a.w, qb[j].w) - fmaxf(a.y, qb[j].y);
                    w = fmaxf(w, 0.0f); h = fmaxf(h, 0.0f);
                    const float inter = w * h;
                    m[j] = __ballot_sync(FULL, 3.0f * inter > ap + qa[j]);
                }
                if (lane == 0) s_sup[p] = make_uint4(m[0], m[1], m[2], m[3]);
            }
        }
    }
    __syncthreads();

    // ---- D: iterated local-max NMS (exactly == sequential greedy) ----
    // Keep every active box whose key beats all active neighbors (greedy
    // picks it before any neighbor), remove kept + suppressed, repeat.
    // Unique keys -> no ties; global max is a local max -> terminates.
    u32 keep0 = 0, keep1 = 0, keep2 = 0, keep3 = 0;
    {
        const int c = wid;
        u32 act[4], k[4];
        #pragma unroll
        for (int w = 0; w < 4; w++) {
            k[w] = s_key[c][lane + 32 * w];
            act[w] = __ballot_sync(FULL, k[w] != 0u);
        }
        for (int pass = 0; pass < NN; ++pass) {
            if (!(act[0] | act[1] | act[2] | act[3])) break;
            u32 lm[4];
            #pragma unroll
            for (int w = 0; w < 4; w++) {
                bool is_lm = false;
                if (act[w] & lane_bit) {
                    const int i = lane + 32 * w;
                    const uint4 row = s_sup[i];
                    u32 n0 = row.x & act[0];
                    u32 n1 = row.y & act[1];
                    u32 n2 = row.z & act[2];
                    u32 n3 = row.w & act[3];
                    if (w == 0) n0 &= ~lane_bit;
                    else if (w == 1) n1 &= ~lane_bit;
                    else if (w == 2) n2 &= ~lane_bit;
                    else n3 &= ~lane_bit;
                    u32 mk = 0;
                    while (n0) { const int q = __ffs(n0) - 1;  n0 &= n0 - 1; mk = max(mk, s_key[c][q]); }
                    while (n1) { const int q = __ffs(n1) + 31; n1 &= n1 - 1; mk = max(mk, s_key[c][q]); }
                    while (n2) { const int q = __ffs(n2) + 63; n2 &= n2 - 1; mk = max(mk, s_key[c][q]); }
                    while (n3) { const int q = __ffs(n3) + 95; n3 &= n3 - 1; mk = max(mk, s_key[c][q]); }
                    is_lm = (k[w] > mk);
                }
                lm[w] = __ballot_sync(FULL, is_lm);
            }
            keep0 |= lm[0]; keep1 |= lm[1]; keep2 |= lm[2]; keep3 |= lm[3];
            #pragma unroll
            for (int w = 0; w < 4; w++) {
                bool rem = false;
                if (act[w] & lane_bit) {
                    const uint4 row = s_sup[lane + 32 * w];
                    rem = ((row.x & lm[0]) | (row.y & lm[1]) |
                           (row.z & lm[2]) | (row.w & lm[3])) != 0u;
                    // kept boxes self-remove via their own row's self bit
                }
                act[w] &= ~__ballot_sync(FULL, rem);
            }
        }
    }

    // ---- E: output, warp = class, float4 stores, multiply-by-kf ----
    // Row per box: [x1,y1,x2,y2,score,keep]*kf. 2 boxes = 3 float4.
    // score reconstructed from key: (key>>7)+BASE; key==0 -> 0.1f*0 = 0.
    {
        const int c = wid;
        const u64 kpLo = (u64)keep0 | ((u64)keep1 << 32);
        const u64 kpHi = (u64)keep2 | ((u64)keep3 << 32);
        float4* op = reinterpret_cast<float4*>(out + ((size_t)batch * NCLS + c) * (NN * 6));
        #pragma unroll
        for (int it = 0; it < 5; ++it) {
            const int v4 = lane + 32 * it;
            if (v4 < 147) {
                const int g = v4 / 3;
                const int part = v4 - 3 * g;
                const int t = 2 * g;
                const float kf0 = ((((t < 64) ? (kpLo >> t) : (kpHi >> (t - 64))) & 1ull) != 0ull) ? 1.0f : 0.0f;
                const float kf1 = ((((t + 1 < 64) ? (kpLo >> (t + 1)) : (kpHi >> (t - 63))) & 1ull) != 0ull) ? 1.0f : 0.0f;
                float4 v;
                if (part == 0) {
                    const float4 b0 = s_box[t];
                    v = make_float4(b0.x * kf0, b0.y * kf0, b0.z * kf0, b0.w * kf0);
                } else if (part == 1) {
                    const float sc0 = __uint_as_float((s_key[c][t] >> 7) + SCORE_BASE);
                    const float4 b1 = s_box[t + 1];
                    v = make_float4(sc0 * kf0, kf0, b1.x * kf1, b1.y * kf1);
                } else {
                    const float4 b1 = s_box[t + 1];
                    const float sc1 = __uint_as_float((s_key[c][t + 1] >> 7) + SCORE_BASE);
                    v = make_float4(b1.z * kf1, b1.w * kf1, sc1 * kf1, kf1);
                }
                op[v4] = v;
            }
        }
    }
}

extern "C" void kernel_launch(void* const* d_in, const int* in_sizes, int n_in,
                              void* d_out, int out_size)
{
    const float* pred = (const float*)d_in[0];
    float* out = (float*)d_out;
    const int bs = in_sizes[0] / PRED_PER_BATCH;
    yolo_nms_kernel<<<bs, NTHREADS>>>(pred, out);
}

// round 9
// speedup vs baseline: 6.3795x; 1.0161x over previous
#include <cuda_runtime.h>
#include <cstdint>

#define SS 7
#define NCLS 20
#define NN 98            // S*S*B
#define NP 128           // padded box count
#define CONF_TH 0.1f
#define NTHREADS 640     // 20 warps, warp = class
#define CH 30            // B*5 + NC
#define PRED_PER_BATCH (SS*SS*CH)   // 1470
#define SCORE_BASE 0x3DCCCCCDu      // float bits of 0.1f

typedef unsigned u32;
typedef unsigned long long u64;

__global__ void __launch_bounds__(NTHREADS, 3)
yolo_nms_kernel(const float* __restrict__ pred, float* __restrict__ out)
{
    __shared__ float  s_pred[PRED_PER_BATCH + 2];
    __shared__ float4 s_box[NP];         // (x1,y1,x2,y2); NaN for pads
    __shared__ float  s_area[NP];        // NaN for pads
    __shared__ u32    s_key[NCLS][NP];   // 0 invalid/pad; ((bits-BASE)<<7)|(127-i)
    __shared__ uint4  s_sup[NN];         // row p: IoU(p,q) > 0.5 bitmask

    const int batch = blockIdx.x;
    const int tid   = threadIdx.x;
    const int wid   = tid >> 5;          // = class
    const int lane  = tid & 31;
    const unsigned FULL = 0xffffffffu;
    const u32 lane_bit = 1u << lane;

    // ---- A: stage pred (float2, coalesced; 1470 floats = 735 f2) ----
    {
        const float2* pb2 = reinterpret_cast<const float2*>(pred + (size_t)batch * PRED_PER_BATCH);
        float2* sp2 = reinterpret_cast<float2*>(s_pred);
        if (tid < 735) {
            sp2[tid] = pb2[tid];
            const int i2 = tid + NTHREADS;          // 640..734 covered by tid<95
            if (i2 < 735) sp2[i2] = pb2[i2];
        }
    }
    __syncthreads();

    // ---- B1: decode boxes -> AoS float4 + area; NaN pads for i >= NN ----
    if (tid < NP) {
        const int i = tid;
        if (i < NN) {
            const int cell = i >> 1, b = i & 1;
            const float* p = s_pred + cell * CH + b * 5;
            const float rowf = (float)(cell / SS);
            const float colf = (float)(cell % SS);
            const float cs = 1.0f / (float)SS;
            float cx = (p[0] + rowf) * cs;
            float cy = (p[1] + colf) * cs;
            float hw = p[2] * 0.5f, hh = p[3] * 0.5f;
            float x1 = fminf(fmaxf(cx - hw, 0.0f), 1.0f);
            float y1 = fminf(fmaxf(cy - hh, 0.0f), 1.0f);
            float x2 = fminf(fmaxf(cx + hw, 0.0f), 1.0f);
            float y2 = fminf(fmaxf(cy + hh, 0.0f), 1.0f);
            s_box[i] = make_float4(x1, y1, x2, y2);
            s_area[i] = (x2 - x1) * (y2 - y1);
        } else {
            const float qn = __uint_as_float(0x7FC00000u);   // NaN
            s_box[i] = make_float4(qn, qn, qn, qn);
            s_area[i] = qn;                                  // sup bit false, no predicate
        }
    }

    // ---- B2: keys (warp = class); zero for invalid and pads ----
    // key preserves exact reference order incl. tie -> lower index:
    // valid scores in (0.1, 1] -> (bits - BASE) < 2^25 -> <<7 fits u32.
    {
        const int c = wid;
        #pragma unroll
        for (int j = 0; j < 4; j++) {
            const int i = lane + 32 * j;
            u32 key = 0;
            if (i < NN) {
                const int cell = i >> 1, b = i & 1;
                const float s = s_pred[cell * CH + 10 + c] * s_pred[cell * CH + b * 5 + 4];
                if (s > CONF_TH)
                    key = ((__float_as_uint(s) - SCORE_BASE) << 7) | (u32)(127 - i);
            }
            s_key[c][i] = key;
        }
    }
    __syncthreads();

    // ---- C: suppression bitmasks; warp w owns rows p = w + 20t ----
    // bit(q): IoU(p,q) > 0.5  <=>  3*inter > area_p + area_q (division-free,
    // symmetric; empirically validated form). NaN pad areas -> false bits.
    {
        float4 qb[4]; float qa[4];
        #pragma unroll
        for (int j = 0; j < 4; j++) {
            const int q = lane + 32 * j;
            qb[j] = s_box[q]; qa[j] = s_area[q];
        }
        #pragma unroll
        for (int t = 0; t < 5; t++) {
            const int p = wid + 20 * t;
            if (p < NN) {
                const float4 a = s_box[p];
                const float ap = s_area[p];
                u32 m[4];
                #pragma unroll
                for (int j = 0; j < 4; j++) {
                    float w = fminf(a.z, qb[j].z) - fmaxf(a.x, qb[j].x);
                    float h = fminf(a.w, qb[j].w) - fmaxf(a.y, qb[j].y);
                    w = fmaxf(w, 0.0f); h = fmaxf(h, 0.0f);
                    const float inter = w * h;
                    m[j] = __ballot_sync(FULL, 3.0f * inter > ap + qa[j]);
                }
                if (lane == 0) s_sup[p] = make_uint4(m[0], m[1], m[2], m[3]);
            }
        }
    }
    __syncthreads();

    // ---- D: iterated local-max NMS (exactly == sequential greedy) ----
    // Keep every active box whose key beats all active neighbors (greedy
    // picks it before any neighbor), remove kept + suppressed, repeat.
    // act[w] is warp-uniform (ballot-maintained), so `if (act[w])` is a
    // uniform branch: dead 32-box words skip their load/mask/ballot cost
    // entirely — passes >= 2 touch only the surviving conflict words.
    u32 keep0 = 0, keep1 = 0, keep2 = 0, keep3 = 0;
    {
        const int c = wid;
        u32 act[4], k[4];
        #pragma unroll
        for (int w = 0; w < 4; w++) {
            k[w] = s_key[c][lane + 32 * w];
            act[w] = __ballot_sync(FULL, k[w] != 0u);
        }
        for (int pass = 0; pass < NN; ++pass) {
            if (!(act[0] | act[1] | act[2] | act[3])) break;
            u32 lm[4];
            #pragma unroll
            for (int w = 0; w < 4; w++) {
                u32 lmw = 0;
                if (act[w]) {                        // uniform skip
                    bool is_lm = false;
                    if (act[w] & lane_bit) {
                        const int i = lane + 32 * w;
                        const uint4 row = s_sup[i];
                        u32 n0 = row.x & act[0];
                        u32 n1 = row.y & act[1];
                        u32 n2 = row.z & act[2];
                        u32 n3 = row.w & act[3];
                        if (w == 0) n0 &= ~lane_bit;
                        else if (w == 1) n1 &= ~lane_bit;
                        else if (w == 2) n2 &= ~lane_bit;
                        else n3 &= ~lane_bit;
                        u32 mk = 0;
                        while (n0) { const int q = __ffs(n0) - 1;  n0 &= n0 - 1; mk = max(mk, s_key[c][q]); }
                        while (n1) { const int q = __ffs(n1) + 31; n1 &= n1 - 1; mk = max(mk, s_key[c][q]); }
                        while (n2) { const int q = __ffs(n2) + 63; n2 &= n2 - 1; mk = max(mk, s_key[c][q]); }
                        while (n3) { const int q = __ffs(n3) + 95; n3 &= n3 - 1; mk = max(mk, s_key[c][q]); }
                        is_lm = (k[w] > mk);
                    }
                    lmw = __ballot_sync(FULL, is_lm);
                }
                lm[w] = lmw;
            }
            keep0 |= lm[0]; keep1 |= lm[1]; keep2 |= lm[2]; keep3 |= lm[3];
            #pragma unroll
            for (int w = 0; w < 4; w++) {
                if (act[w]) {                        // uniform skip
                    bool rem = false;
                    if (act[w] & lane_bit) {
                        const uint4 row = s_sup[lane + 32 * w];
                        rem = ((row.x & lm[0]) | (row.y & lm[1]) |
                               (row.z & lm[2]) | (row.w & lm[3])) != 0u;
                        // kept boxes self-remove via their own row's self bit
                    }
                    act[w] &= ~__ballot_sync(FULL, rem);
                }
            }
        }
    }

    // ---- E: output, warp = class, float4 stores, multiply-by-kf ----
    // Row per box: [x1,y1,x2,y2,score,keep]*kf. 2 boxes = 3 float4.
    // score reconstructed from key: (key>>7)+BASE; key==0 -> 0.1f*0 = 0.
    // Iterations 0..3 have v4 <= 127 < 147: no bounds check needed.
    {
        const int c = wid;
        const u64 kpLo = (u64)keep0 | ((u64)keep1 << 32);
        const u64 kpHi = (u64)keep2 | ((u64)keep3 << 32);
        float4* op = reinterpret_cast<float4*>(out + ((size_t)batch * NCLS + c) * (NN * 6));
        #pragma unroll
        for (int it = 0; it < 5; ++it) {
            const int v4 = lane + 32 * it;
            if (it == 4 && v4 >= 147) break;
            const int g = v4 / 3;
            const int part = v4 - 3 * g;
            const int t = 2 * g;
            const float kf0 = ((((t < 64) ? (kpLo >> t) : (kpHi >> (t - 64))) & 1ull) != 0ull) ? 1.0f : 0.0f;
            const float kf1 = ((((t + 1 < 64) ? (kpLo >> (t + 1)) : (kpHi >> (t - 63))) & 1ull) != 0ull) ? 1.0f : 0.0f;
            float4 v;
            if (part == 0) {
                const float4 b0 = s_box[t];
                v = make_float4(b0.x * kf0, b0.y * kf0, b0.z * kf0, b0.w * kf0);
            } else if (part == 1) {
                const float sc0 = __uint_as_float((s_key[c][t] >> 7) + SCORE_BASE);
                const float4 b1 = s_box[t + 1];
                v = make_float4(sc0 * kf0, kf0, b1.x * kf1, b1.y * kf1);
            } else {
                const float4 b1 = s_box[t + 1];
                const float sc1 = __uint_as_float((s_key[c][t + 1] >> 7) + SCORE_BASE);
                v = make_float4(b1.z * kf1, b1.w * kf1, sc1 * kf1, kf1);
            }
            op[v4] = v;
        }
    }
}

extern "C" void kernel_launch(void* const* d_in, const int* in_sizes, int n_in,
                              void* d_out, int out_size)
{
    const float* pred = (const float*)d_in[0];
    float* out = (float*)d_out;
    const int bs = in_sizes[0] / PRED_PER_BATCH;
    yolo_nms_kernel<<<bs, NTHREADS>>>(pred, out);
}